// round 1
// baseline (speedup 1.0000x reference)
#include <cuda_runtime.h>
#include <cuda_bf16.h>

// Spatial-grid exact nearest neighbor.
// Grid: 256x256 bins over [0,10]^2, ~15.3 pts/bin expected (L=1e6).
// CAP=96 per bin (Poisson(15.3) tail beyond 96 ~ 0), overflow list for exactness.

#define GRIDW   256
#define NBINS   (GRIDW * GRIDW)
#define CAP     96
#define OVF_CAP 8192
#define WORLD   10.0f
#define CELLW   (WORLD / (float)GRIDW)      /* 0.0390625, exact in fp32 */
#define INVCELL ((float)GRIDW / WORLD)      /* 25.6 */

__device__ int g_bin_count[NBINS];
__device__ int g_bin_idx[NBINS * CAP];
__device__ int g_ovf_cnt;
__device__ int g_ovf_idx[OVF_CAP];

__global__ void k_zero()
{
    int i = blockIdx.x * blockDim.x + threadIdx.x;
    if (i < NBINS) g_bin_count[i] = 0;
    if (i == 0)    g_ovf_cnt = 0;
}

// Fused: write input_tensor rows (X, Y, 0) AND scatter point index into its bin.
__global__ void k_scatter(const float2* __restrict__ mesh,
                          float* __restrict__ out, int L)
{
    int i = blockIdx.x * blockDim.x + threadIdx.x;
    if (i >= L) return;
    float2 p = mesh[i];
    out[3 * i + 0] = p.x;
    out[3 * i + 1] = p.y;
    out[3 * i + 2] = 0.0f;

    int bx = (int)(p.x * INVCELL); bx = max(0, min(GRIDW - 1, bx));
    int by = (int)(p.y * INVCELL); by = max(0, min(GRIDW - 1, by));
    int bin = by * GRIDW + bx;
    int slot = atomicAdd(&g_bin_count[bin], 1);
    if (slot < CAP) {
        g_bin_idx[bin * CAP + slot] = i;
    } else {
        int o = atomicAdd(&g_ovf_cnt, 1);
        if (o < OVF_CAP) g_ovf_idx[o] = i;
    }
}

__device__ __forceinline__ void lexmin(float d2, int idx, float& bd, int& bi)
{
    // matches jnp.argmin tie-break: min d2, then smallest index
    if (d2 < bd || (d2 == bd && idx < bi)) { bd = d2; bi = idx; }
}

// One warp per receiver: expanding-ring exact NN search.
__global__ void k_query(const float2* __restrict__ mesh,
                        const float* __restrict__ rp,
                        float* __restrict__ out, int L, int B)
{
    int wid  = (blockIdx.x * blockDim.x + threadIdx.x) >> 5;
    int lane = threadIdx.x & 31;
    if (wid >= B) return;

    float rx = rp[3 * wid + 0];
    float ry = rp[3 * wid + 1];
    int bx = max(0, min(GRIDW - 1, (int)(rx * INVCELL)));
    int by = max(0, min(GRIDW - 1, (int)(ry * INVCELL)));

    float bd = __int_as_float(0x7f800000);  // +inf
    int   bi = 0x7fffffff;

    for (int r = 0; r < GRIDW; ++r) {
        // Any cell at Chebyshev ring r is >= (r-1)*CELLW away from the receiver.
        if (r > 0 && bi != 0x7fffffff) {
            float t = (float)(r - 1) * CELLW;
            if (t * t > bd) break;
        }
        int x0 = bx - r, x1 = bx + r, y0 = by - r, y1 = by + r;
        #pragma unroll
        for (int pass = 0; pass < 4; ++pass) {
            int cx0, cx1, cy0, cy1;
            if (pass == 0)      { cy0 = y0; cy1 = y0; cx0 = x0; cx1 = x1; }
            else if (pass == 1) { if (r == 0) continue; cy0 = y1; cy1 = y1; cx0 = x0; cx1 = x1; }
            else if (pass == 2) { if (r == 0) continue; cx0 = x0; cx1 = x0; cy0 = y0 + 1; cy1 = y1 - 1; }
            else                { if (r == 0) continue; cx0 = x1; cx1 = x1; cy0 = y0 + 1; cy1 = y1 - 1; }
            cy0 = max(cy0, 0); cy1 = min(cy1, GRIDW - 1);
            cx0 = max(cx0, 0); cx1 = min(cx1, GRIDW - 1);
            for (int cy = cy0; cy <= cy1; ++cy) {
                for (int cx = cx0; cx <= cx1; ++cx) {
                    int bin = cy * GRIDW + cx;
                    int cnt = min(g_bin_count[bin], CAP);
                    for (int j = lane; j < cnt; j += 32) {
                        int idx  = g_bin_idx[bin * CAP + j];
                        float2 p = mesh[idx];
                        float dx = p.x - rx, dy = p.y - ry;
                        lexmin(fmaf(dx, dx, dy * dy), idx, bd, bi);
                    }
                }
            }
        }
        // warp-wide lexicographic min so the stop bound is uniform
        #pragma unroll
        for (int off = 16; off; off >>= 1) {
            float od = __shfl_xor_sync(0xffffffffu, bd, off);
            int   oi = __shfl_xor_sync(0xffffffffu, bi, off);
            lexmin(od, oi, bd, bi);
        }
    }

    // overflow list (normally empty) — scan unconditionally for exactness
    int oc = min(g_ovf_cnt, OVF_CAP);
    for (int j = lane; j < oc; j += 32) {
        int idx  = g_ovf_idx[j];
        float2 p = mesh[idx];
        float dx = p.x - rx, dy = p.y - ry;
        lexmin(fmaf(dx, dx, dy * dy), idx, bd, bi);
    }
    #pragma unroll
    for (int off = 16; off; off >>= 1) {
        float od = __shfl_xor_sync(0xffffffffu, bd, off);
        int   oi = __shfl_xor_sync(0xffffffffu, bi, off);
        lexmin(od, oi, bd, bi);
    }

    if (lane == 0) {
        float2 q = mesh[bi];
        int base = 3 * L;
        out[base + 2 * wid + 0] = q.x;             // closest_points x
        out[base + 2 * wid + 1] = q.y;             // closest_points y
        out[base + 2 * B + wid] = (float)bi;       // min_index (as float)
        out[3 * bi + 2] = 1.0f;                    // one_hot at min_index
        if (wid == 0 && B > 1) out[2] = 1.0f;      // one_hot[0] forced
    }
}

extern "C" void kernel_launch(void* const* d_in, const int* in_sizes, int n_in,
                              void* d_out, int out_size)
{
    const float2* mesh = (const float2*)d_in[0];
    const float*  rp   = (const float*)d_in[1];
    float*        out  = (float*)d_out;
    int L = in_sizes[0] / 2;
    int B = in_sizes[1] / 3;

    k_zero<<<(NBINS + 255) / 256, 256>>>();
    k_scatter<<<(L + 255) / 256, 256>>>(mesh, out, L);
    k_query<<<(B * 32 + 255) / 256, 256>>>(mesh, rp, out, L, B);
}

// round 2
// speedup vs baseline: 1.1952x; 1.1952x over previous
#include <cuda_runtime.h>
#include <cuda_bf16.h>

// Spatial-grid exact nearest neighbor.
// Grid: 256x256 bins over [0,10]^2, ~15.3 pts/bin expected (L=1e6).
// CAP=96 per bin, overflow list guarantees exactness on spill.

#define GRIDW   256
#define NBINS   (GRIDW * GRIDW)
#define CAP     96
#define OVF_CAP 8192
#define WORLD   10.0f
#define CELLW   (WORLD / (float)GRIDW)      /* 0.0390625, exact in fp32 */
#define INVCELL ((float)GRIDW / WORLD)      /* 25.6 */

__device__ int g_bin_count[NBINS];
__device__ int g_bin_idx[NBINS * CAP];
__device__ int g_ovf_cnt;
__device__ int g_ovf_idx[OVF_CAP];

__device__ __forceinline__ void bin_one(float x, float y, int idx)
{
    int bx = (int)(x * INVCELL); bx = max(0, min(GRIDW - 1, bx));
    int by = (int)(y * INVCELL); by = max(0, min(GRIDW - 1, by));
    int bin = by * GRIDW + bx;
    int slot = atomicAdd(&g_bin_count[bin], 1);
    if (slot < CAP) {
        g_bin_idx[bin * CAP + slot] = idx;
    } else {
        int o = atomicAdd(&g_ovf_cnt, 1);
        if (o < OVF_CAP) g_ovf_idx[o] = idx;
    }
}

// Fused: write input_tensor rows (X, Y, 0) with float4 stores AND scatter
// point indices into bins. 4 points per thread.
__global__ void k_scatter(const float4* __restrict__ mesh4,
                          float4* __restrict__ out4,
                          const float2* __restrict__ mesh,
                          float* __restrict__ out, int L)
{
    int i = blockIdx.x * blockDim.x + threadIdx.x;
    int L4 = L >> 2;
    if (i < L4) {
        float4 a = mesh4[2 * i];       // p0=(a.x,a.y) p1=(a.z,a.w)
        float4 b = mesh4[2 * i + 1];   // p2=(b.x,b.y) p3=(b.z,b.w)
        out4[3 * i + 0] = make_float4(a.x, a.y, 0.f, a.z);
        out4[3 * i + 1] = make_float4(a.w, 0.f, b.x, b.y);
        out4[3 * i + 2] = make_float4(0.f, b.z, b.w, 0.f);
        int base = 4 * i;
        bin_one(a.x, a.y, base + 0);
        bin_one(a.z, a.w, base + 1);
        bin_one(b.x, b.y, base + 2);
        bin_one(b.z, b.w, base + 3);
    }
    // tail (L not multiple of 4)
    int t = L4 * 4 + i;
    if (i < (L & 3) && t < L) {
        float2 p = mesh[t];
        out[3 * t + 0] = p.x;
        out[3 * t + 1] = p.y;
        out[3 * t + 2] = 0.0f;
        bin_one(p.x, p.y, t);
    }
}

__device__ __forceinline__ void lexmin(float d2, int idx, float& bd, int& bi)
{
    // matches jnp.argmin tie-break: min d2, then smallest index
    if (d2 < bd || (d2 == bd && idx < bi)) { bd = d2; bi = idx; }
}

__device__ __forceinline__ void warp_reduce_lexmin(float& bd, int& bi)
{
    #pragma unroll
    for (int off = 16; off; off >>= 1) {
        float od = __shfl_xor_sync(0xffffffffu, bd, off);
        int   oi = __shfl_xor_sync(0xffffffffu, bi, off);
        lexmin(od, oi, bd, bi);
    }
}

// One warp per receiver. Fast path: flatten the 3x3 cell neighborhood into
// one lane-strided candidate list (all counts loaded in parallel, all idx
// loads issued together, all mesh gathers pipelined). Fallback: expanding
// rings from r=2 (rare).
__global__ void k_query(const float2* __restrict__ mesh,
                        const float* __restrict__ rp,
                        float* __restrict__ out, int L, int B)
{
    int wid  = (blockIdx.x * blockDim.x + threadIdx.x) >> 5;
    int lane = threadIdx.x & 31;
    if (wid >= B) return;

    float rx = rp[3 * wid + 0];
    float ry = rp[3 * wid + 1];
    int bx = max(0, min(GRIDW - 1, (int)(rx * INVCELL)));
    int by = max(0, min(GRIDW - 1, (int)(ry * INVCELL)));

    float bd = __int_as_float(0x7f800000);  // +inf
    int   bi = 0x7fffffff;

    // ---- fast path: 3x3 neighborhood, parallel counts ----
    int cnt_l = 0, bin_l = 0;
    if (lane < 9) {
        int cx = bx + (lane % 3) - 1;
        int cy = by + (lane / 3) - 1;
        if (cx >= 0 && cx < GRIDW && cy >= 0 && cy < GRIDW) {
            bin_l = cy * GRIDW + cx;
            cnt_l = min(g_bin_count[bin_l], CAP);
        }
    }
    int cnts[9], bins[9], pre[9];
    int total = 0;
    #pragma unroll
    for (int c = 0; c < 9; ++c) {
        cnts[c] = __shfl_sync(0xffffffffu, cnt_l, c);
        bins[c] = __shfl_sync(0xffffffffu, bin_l, c);
        pre[c]  = total;
        total  += cnts[c];
    }
    for (int t = lane; t < total; t += 32) {
        int c = 0;
        #pragma unroll
        for (int k = 1; k < 9; ++k) if (t >= pre[k]) c = k;
        int slot = t - pre[c];
        int idx  = g_bin_idx[bins[c] * CAP + slot];
        float2 p = mesh[idx];
        float dx = p.x - rx, dy = p.y - ry;
        lexmin(fmaf(dx, dx, dy * dy), idx, bd, bi);
    }
    warp_reduce_lexmin(bd, bi);

    // Proof bound: every unscanned cell (Chebyshev ring >= 2) is at distance
    // >= CELLW from the receiver. Small fp slack keeps the proof exact.
    bool done = (bi != 0x7fffffff) && (bd < CELLW * CELLW * 0.99998f);

    if (!done) {
        // ---- fallback: expanding ring perimeters from r=2 ----
        for (int r = 2; r < GRIDW; ++r) {
            if (bi != 0x7fffffff) {
                float t = (float)(r - 1) * CELLW;
                if (t * t > bd) break;
            }
            int x0 = bx - r, x1 = bx + r, y0 = by - r, y1 = by + r;
            #pragma unroll
            for (int pass = 0; pass < 4; ++pass) {
                int cx0, cx1, cy0, cy1;
                if (pass == 0)      { cy0 = y0; cy1 = y0; cx0 = x0; cx1 = x1; }
                else if (pass == 1) { cy0 = y1; cy1 = y1; cx0 = x0; cx1 = x1; }
                else if (pass == 2) { cx0 = x0; cx1 = x0; cy0 = y0 + 1; cy1 = y1 - 1; }
                else                { cx0 = x1; cx1 = x1; cy0 = y0 + 1; cy1 = y1 - 1; }
                cy0 = max(cy0, 0); cy1 = min(cy1, GRIDW - 1);
                cx0 = max(cx0, 0); cx1 = min(cx1, GRIDW - 1);
                for (int cy = cy0; cy <= cy1; ++cy) {
                    for (int cx = cx0; cx <= cx1; ++cx) {
                        int bin = cy * GRIDW + cx;
                        int cnt = min(g_bin_count[bin], CAP);
                        for (int j = lane; j < cnt; j += 32) {
                            int idx  = g_bin_idx[bin * CAP + j];
                            float2 p = mesh[idx];
                            float dx = p.x - rx, dy = p.y - ry;
                            lexmin(fmaf(dx, dx, dy * dy), idx, bd, bi);
                        }
                    }
                }
            }
            warp_reduce_lexmin(bd, bi);
        }
    }

    // overflow list (normally empty) — scan unconditionally for exactness
    int oc = min(g_ovf_cnt, OVF_CAP);
    if (oc > 0) {
        for (int j = lane; j < oc; j += 32) {
            int idx  = g_ovf_idx[j];
            float2 p = mesh[idx];
            float dx = p.x - rx, dy = p.y - ry;
            lexmin(fmaf(dx, dx, dy * dy), idx, bd, bi);
        }
        warp_reduce_lexmin(bd, bi);
    }

    if (lane == 0) {
        float2 q = mesh[bi];
        int base = 3 * L;
        out[base + 2 * wid + 0] = q.x;             // closest_points x
        out[base + 2 * wid + 1] = q.y;             // closest_points y
        out[base + 2 * B + wid] = (float)bi;       // min_index (as float)
        out[3 * bi + 2] = 1.0f;                    // one_hot at min_index
        if (wid == 0 && B > 1) out[2] = 1.0f;      // one_hot[0] forced
    }
}

extern "C" void kernel_launch(void* const* d_in, const int* in_sizes, int n_in,
                              void* d_out, int out_size)
{
    const float2* mesh = (const float2*)d_in[0];
    const float*  rp   = (const float*)d_in[1];
    float*        out  = (float*)d_out;
    int L = in_sizes[0] / 2;
    int B = in_sizes[1] / 3;

    void *pc = nullptr, *po = nullptr;
    cudaGetSymbolAddress(&pc, g_bin_count);
    cudaGetSymbolAddress(&po, g_ovf_cnt);
    cudaMemsetAsync(pc, 0, NBINS * sizeof(int));
    cudaMemsetAsync(po, 0, sizeof(int));

    int L4 = (L + 3) / 4;
    k_scatter<<<(L4 + 255) / 256, 256>>>((const float4*)mesh, (float4*)out,
                                         mesh, out, L);
    k_query<<<(B * 32 + 255) / 256, 256>>>(mesh, rp, out, L, B);
}

// round 4
// speedup vs baseline: 1.4565x; 1.2187x over previous
#include <cuda_runtime.h>
#include <cuda_bf16.h>

// Spatial-grid exact nearest neighbor.
// 256x256 bins over [0,10]^2, ~15.3 pts/bin (L=1e6). CAP=32 (one 128B line
// per bin); spills go to an overflow list scanned by every query block, so
// the result is exact and deterministic regardless of atomic ordering.

#define GRIDW   256
#define NBINS   (GRIDW * GRIDW)
#define CAP     32
#define OVF_CAP 8192
#define WORLD   10.0f
#define CELLW   (WORLD / (float)GRIDW)      /* 0.0390625, exact in fp32 */
#define INVCELL ((float)GRIDW / WORLD)      /* 25.6 */

__device__ int g_bin_count[NBINS + 1];      // [NBINS] = overflow counter
__device__ int g_bin_idx[NBINS * CAP];
__device__ int g_ovf_idx[OVF_CAP];

__device__ __forceinline__ void bin_one(float x, float y, int idx)
{
    int bx = (int)(x * INVCELL); bx = max(0, min(GRIDW - 1, bx));
    int by = (int)(y * INVCELL); by = max(0, min(GRIDW - 1, by));
    int bin = by * GRIDW + bx;
    int slot = atomicAdd(&g_bin_count[bin], 1);
    if (slot < CAP) {
        g_bin_idx[bin * CAP + slot] = idx;
    } else {
        int o = atomicAdd(&g_bin_count[NBINS], 1);
        if (o < OVF_CAP) g_ovf_idx[o] = idx;
    }
}

// Fused: write input_tensor rows (X, Y, 0) with float4 stores AND scatter
// point indices into bins. 4 points per thread.
__global__ void k_scatter(const float4* __restrict__ mesh4,
                          float4* __restrict__ out4,
                          const float2* __restrict__ mesh,
                          float* __restrict__ out, int L)
{
    int i = blockIdx.x * blockDim.x + threadIdx.x;
    int L4 = L >> 2;
    if (i < L4) {
        float4 a = mesh4[2 * i];       // p0=(a.x,a.y) p1=(a.z,a.w)
        float4 b = mesh4[2 * i + 1];   // p2=(b.x,b.y) p3=(b.z,b.w)
        out4[3 * i + 0] = make_float4(a.x, a.y, 0.f, a.z);
        out4[3 * i + 1] = make_float4(a.w, 0.f, b.x, b.y);
        out4[3 * i + 2] = make_float4(0.f, b.z, b.w, 0.f);
        int base = 4 * i;
        bin_one(a.x, a.y, base + 0);
        bin_one(a.z, a.w, base + 1);
        bin_one(b.x, b.y, base + 2);
        bin_one(b.z, b.w, base + 3);
    }
    // tail (L not multiple of 4)
    int t = L4 * 4 + i;
    if (i < (L & 3) && t < L) {
        float2 p = mesh[t];
        out[3 * t + 0] = p.x;
        out[3 * t + 1] = p.y;
        out[3 * t + 2] = 0.0f;
        bin_one(p.x, p.y, t);
    }
}

__device__ __forceinline__ unsigned long long
pack_key(float d2, int idx)
{
    // d2 >= 0 so float bits are order-preserving; low 32 bits = index gives
    // jnp.argmin's first-index tie-break under 64-bit unsigned min.
    return ((unsigned long long)__float_as_uint(d2) << 32) | (unsigned)idx;
}

// One block (288 threads) per receiver: every 3x3-neighborhood candidate gets
// its own thread -> a single dependent load chain, then atomicMin reduction.
__global__ void __launch_bounds__(288)
k_query(const float2* __restrict__ mesh,
        const float* __restrict__ rp,
        float* __restrict__ out, int L, int B)
{
    int b = blockIdx.x;
    int t = threadIdx.x;

    __shared__ int s_cnt[9], s_bin[9], s_pre[10];
    __shared__ unsigned long long s_key;
    __shared__ float s_rx, s_ry;
    __shared__ int s_bx, s_by;

    if (t == 0) {
        float rx = rp[3 * b], ry = rp[3 * b + 1];
        s_rx = rx; s_ry = ry;
        s_bx = max(0, min(GRIDW - 1, (int)(rx * INVCELL)));
        s_by = max(0, min(GRIDW - 1, (int)(ry * INVCELL)));
        s_key = ~0ull;
    }
    __syncthreads();

    if (t < 9) {
        int cx = s_bx + (t % 3) - 1;
        int cy = s_by + (t / 3) - 1;
        int c = 0, bin = 0;
        if (cx >= 0 && cx < GRIDW && cy >= 0 && cy < GRIDW) {
            bin = cy * GRIDW + cx;
            c = min(g_bin_count[bin], CAP);
        }
        s_cnt[t] = c; s_bin[t] = bin;
    }
    __syncthreads();
    if (t == 0) {
        int acc = 0;
        #pragma unroll
        for (int k = 0; k < 9; ++k) { s_pre[k] = acc; acc += s_cnt[k]; }
        s_pre[9] = acc;
    }
    __syncthreads();

    float rx = s_rx, ry = s_ry;
    int total = s_pre[9];
    unsigned long long mykey = ~0ull;

    for (int q = t; q < total; q += blockDim.x) {
        int c = 0;
        #pragma unroll
        for (int k = 1; k < 9; ++k) if (q >= s_pre[k]) c = k;
        int idx  = g_bin_idx[s_bin[c] * CAP + (q - s_pre[c])];
        float2 p = mesh[idx];
        float dx = p.x - rx, dy = p.y - ry;
        unsigned long long key = pack_key(fmaf(dx, dx, dy * dy), idx);
        if (key < mykey) mykey = key;
    }
    // overflow list (normally ~empty) — scanned by every block for exactness
    int oc = min(g_bin_count[NBINS], OVF_CAP);
    for (int q = t; q < oc; q += blockDim.x) {
        int idx  = g_ovf_idx[q];
        float2 p = mesh[idx];
        float dx = p.x - rx, dy = p.y - ry;
        unsigned long long key = pack_key(fmaf(dx, dx, dy * dy), idx);
        if (key < mykey) mykey = key;
    }
    if (mykey != ~0ull) atomicMin(&s_key, mykey);
    __syncthreads();

    // Proof bound: any unscanned cell (Chebyshev ring >= 2) is >= CELLW away.
    unsigned long long k0 = s_key;
    float bd0 = __uint_as_float((unsigned)(k0 >> 32));
    bool need_fb = (k0 == ~0ull) || !(bd0 < CELLW * CELLW * 0.99998f);

    if (need_fb && t < 32) {  // rare: expanding-ring exact search, warp 0
        int lane = t;
        float bd = (k0 == ~0ull) ? __int_as_float(0x7f800000) : bd0;
        int   bi = (k0 == ~0ull) ? 0x7fffffff : (int)(unsigned)k0;
        int bx = s_bx, by = s_by;
        for (int r = 2; r < GRIDW; ++r) {
            if (bi != 0x7fffffff) {
                float tb = (float)(r - 1) * CELLW;
                if (tb * tb > bd) break;
            }
            int x0 = bx - r, x1 = bx + r, y0 = by - r, y1 = by + r;
            #pragma unroll
            for (int pass = 0; pass < 4; ++pass) {
                int cx0, cx1, cy0, cy1;
                if (pass == 0)      { cy0 = y0; cy1 = y0; cx0 = x0; cx1 = x1; }
                else if (pass == 1) { cy0 = y1; cy1 = y1; cx0 = x0; cx1 = x1; }
                else if (pass == 2) { cx0 = x0; cx1 = x0; cy0 = y0 + 1; cy1 = y1 - 1; }
                else                { cx0 = x1; cx1 = x1; cy0 = y0 + 1; cy1 = y1 - 1; }
                cy0 = max(cy0, 0); cy1 = min(cy1, GRIDW - 1);
                cx0 = max(cx0, 0); cx1 = min(cx1, GRIDW - 1);
                for (int cy = cy0; cy <= cy1; ++cy)
                    for (int cx = cx0; cx <= cx1; ++cx) {
                        int bin = cy * GRIDW + cx;
                        int cnt = min(g_bin_count[bin], CAP);
                        for (int j = lane; j < cnt; j += 32) {
                            int idx  = g_bin_idx[bin * CAP + j];
                            float2 p = mesh[idx];
                            float dx = p.x - rx, dy = p.y - ry;
                            float d2 = fmaf(dx, dx, dy * dy);
                            if (d2 < bd || (d2 == bd && idx < bi)) { bd = d2; bi = idx; }
                        }
                    }
            }
            unsigned long long wk = pack_key(bd, bi);
            #pragma unroll
            for (int off = 16; off; off >>= 1) {
                unsigned long long ok = __shfl_xor_sync(0xffffffffu, wk, off);
                if (ok < wk) wk = ok;
            }
            bd = __uint_as_float((unsigned)(wk >> 32));
            bi = (int)(unsigned)wk;
        }
        if (lane == 0) atomicMin(&s_key, pack_key(bd, bi));
    }
    __syncthreads();

    if (t == 0) {
        int bi = (int)(unsigned)s_key;
        float2 q = mesh[bi];
        int base = 3 * L;
        out[base + 2 * b + 0] = q.x;           // closest_points x
        out[base + 2 * b + 1] = q.y;           // closest_points y
        out[base + 2 * B + b] = (float)bi;     // min_index (as float)
        out[3 * bi + 2] = 1.0f;                // one_hot at min_index
        if (b == 0 && B > 1) out[2] = 1.0f;    // one_hot[0] forced
    }
}

extern "C" void kernel_launch(void* const* d_in, const int* in_sizes, int n_in,
                              void* d_out, int out_size)
{
    const float2* mesh = (const float2*)d_in[0];
    const float*  rp   = (const float*)d_in[1];
    float*        out  = (float*)d_out;
    int L = in_sizes[0] / 2;
    int B = in_sizes[1] / 3;

    void* pc = nullptr;
    cudaGetSymbolAddress(&pc, g_bin_count);
    cudaMemsetAsync(pc, 0, (NBINS + 1) * sizeof(int));

    int L4 = (L + 3) / 4;
    k_scatter<<<(L4 + 255) / 256, 256>>>((const float4*)mesh, (float4*)out,
                                         mesh, out, L);
    k_query<<<B, 288>>>(mesh, rp, out, L, B);
}